// round 10
// baseline (speedup 1.0000x reference)
#include <cuda_runtime.h>
#include <cuda_bf16.h>
#include <cstdint>

#define BATCH    1024
#define NS       64
#define EM_T     65536u      // floats per timestep (B*NS)
#define SHIFT_C  4.5f

__device__ int g_perm[BATCH];   // rank (desc by length) -> batch index

// ---- rank by length (descending), ties by index: perm is a bijection ----
__global__ void rank_kernel(const int* __restrict__ seq) {
    __shared__ int len[BATCH];
    const int tid = threadIdx.x;             // 128 threads
    for (int j = tid; j < BATCH; j += 128) len[j] = seq[j];
    __syncthreads();
    const int i  = blockIdx.x * 128 + tid;
    const int li = len[i];
    int r = 0;
#pragma unroll 8
    for (int j = 0; j < BATCH; j++) {
        int lj = len[j];
        r += (int)((lj > li) | ((lj == li) & (j < i)));
    }
    g_perm[r] = i;
}

__device__ __forceinline__ unsigned pack_bf2(float lo, float hi) {
    __nv_bfloat162 h = __floats2bfloat162_rn(lo, hi);
    return *reinterpret_cast<unsigned*>(&h);
}
__device__ __forceinline__ uint16_t bf16b(float x) {
    __nv_bfloat16 h = __float2bfloat16(x);
    return *reinterpret_cast<uint16_t*>(&h);
}
__device__ __forceinline__ float bf16lo_f(unsigned u) {
    __nv_bfloat162 h = *reinterpret_cast<__nv_bfloat162*>(&u);
    return __low2float(h);
}

__device__ __forceinline__ void mma16816(float* d, const unsigned* a,
                                         unsigned b0, unsigned b1) {
    asm("mma.sync.aligned.m16n8k16.row.col.f32.bf16.bf16.f32 "
        "{%0,%1,%2,%3}, {%4,%5,%6,%7}, {%8,%9}, {%0,%1,%2,%3};"
        : "+f"(d[0]), "+f"(d[1]), "+f"(d[2]), "+f"(d[3])
        : "r"(a[0]), "r"(a[1]), "r"(a[2]), "r"(a[3]), "r"(b0), "r"(b1));
}

// Block = one group of 8 length-sorted sequences. 256 thr: warps 0-3 = forward
// unit, warps 4-7 = backward unit. Each warp owns 16 output states. Per tick:
// V'[64x8] = E[64x64] @ V[64x8] via 4x mma.m16n8k16 (bf16 in, f32 accum),
// exchanged through a double-buffered smem tile. f32 master state per thread.
__global__ void __launch_bounds__(256, 1)
crf_forward_kernel(const float* __restrict__ em,
                   const int*   __restrict__ seq,
                   const float* __restrict__ start,
                   const float* __restrict__ stop,
                   const float* __restrict__ trans,
                   float*       __restrict__ out)
{
    __shared__ unsigned vbuf[2][2][32][8];   // [unit][parity][kpair][n]
    __shared__ float meetA[NS][8];
    __shared__ float meetB[NS][8];
    __shared__ float sCf[8], sCb[8];
    __shared__ int   bat[8], Lsh[8];

    const int tid  = threadIdx.x;
    const int w    = tid >> 5;
    const int lane = tid & 31;
    const int unit = w >> 2;                 // 0 fwd, 1 bwd
    const int wu   = w & 3;                  // warp-in-unit: rows [16wu,16wu+16)
    const int gid  = lane >> 2;              // 0..7
    const int tig  = lane & 3;               // 0..3

    if (tid < 8) {
        int b = g_perm[8 * blockIdx.x + tid];
        bat[tid] = b;
        Lsh[tid] = seq[b];
    }
    __syncthreads();

    const int c0 = 2 * tig, c1 = c0 + 1;     // my 2 columns (sequences)
    const int R0 = 16 * wu + gid, R1 = R0 + 8;  // my 2 output rows (states)
    const int b0 = bat[c0], b1 = bat[c1];
    const int L0 = Lsh[c0], L1 = Lsh[c1];
    // my role's step counts per column
    const int S0 = unit ? (L0 - 1 - (L0 >> 1)) : (L0 >> 1);
    const int S1 = unit ? (L1 - 1 - (L1 >> 1)) : (L1 >> 1);
    int Tmax = 0;
#pragma unroll
    for (int j = 0; j < 8; j++) {
        int Lj = Lsh[j];
        int s  = unit ? (Lj - 1 - (Lj >> 1)) : (Lj >> 1);
        Tmax = max(Tmax, s);
    }

    // ---- one-time A fragments: fwd rows of E, bwd rows of E^T ----
    unsigned afr[4][4];
    if (unit == 0) {
#pragma unroll
        for (int kt = 0; kt < 4; kt++) {
            int kc = 16 * kt + 2 * tig;
            float2 x0 = *(const float2*)(trans + R0 * NS + kc);
            float2 x1 = *(const float2*)(trans + R1 * NS + kc);
            float2 x2 = *(const float2*)(trans + R0 * NS + kc + 8);
            float2 x3 = *(const float2*)(trans + R1 * NS + kc + 8);
            afr[kt][0] = pack_bf2(__expf(x0.x - SHIFT_C), __expf(x0.y - SHIFT_C));
            afr[kt][1] = pack_bf2(__expf(x1.x - SHIFT_C), __expf(x1.y - SHIFT_C));
            afr[kt][2] = pack_bf2(__expf(x2.x - SHIFT_C), __expf(x2.y - SHIFT_C));
            afr[kt][3] = pack_bf2(__expf(x3.x - SHIFT_C), __expf(x3.y - SHIFT_C));
        }
    } else {
#pragma unroll
        for (int kt = 0; kt < 4; kt++) {
            int kc = 16 * kt + 2 * tig;
            afr[kt][0] = pack_bf2(__expf(__ldg(trans + kc * NS + R0) - SHIFT_C),
                                  __expf(__ldg(trans + (kc + 1) * NS + R0) - SHIFT_C));
            afr[kt][1] = pack_bf2(__expf(__ldg(trans + kc * NS + R1) - SHIFT_C),
                                  __expf(__ldg(trans + (kc + 1) * NS + R1) - SHIFT_C));
            afr[kt][2] = pack_bf2(__expf(__ldg(trans + (kc + 8) * NS + R0) - SHIFT_C),
                                  __expf(__ldg(trans + (kc + 9) * NS + R0) - SHIFT_C));
            afr[kt][3] = pack_bf2(__expf(__ldg(trans + (kc + 8) * NS + R1) - SHIFT_C),
                                  __expf(__ldg(trans + (kc + 9) * NS + R1) - SHIFT_C));
        }
    }

    // emission pointers for my 4 (row, col) elements: d0=(R0,c0) d1=(R0,c1) d2=(R1,c0) d3=(R1,c1)
    const float* p00 = em + (unsigned)b0 * NS + R0;
    const float* p01 = em + (unsigned)b1 * NS + R0;
    const float* p10 = em + (unsigned)b0 * NS + R1;
    const float* p11 = em + (unsigned)b1 * NS + R1;

    // f32 master state + per-column log-scale accumulators
    float V0, V1, V2, V3;
    float Ca = 0.0f, Cc = 0.0f;
    if (unit == 0) {
        float s0v = __ldg(start + R0), s1v = __ldg(start + R1);
        V0 = __expf(s0v + __ldg(p00));
        V1 = __expf(s0v + __ldg(p01));
        V2 = __expf(s1v + __ldg(p10));
        V3 = __expf(s1v + __ldg(p11));
    } else {
        float t0 = __expf(__ldg(stop + R0));
        float t1 = __expf(__ldg(stop + R1));
        V0 = t0; V1 = t1; V2 = t0; V3 = t1;
        // careful: d-order is (R0,c0),(R0,c1),(R1,c0),(R1,c1) -> stop depends on row only
        V0 = t0; V1 = t0; V2 = t1; V3 = t1;
    }

    // raw emission ring, 4 ticks deep. fwd slot j: t=1+j. bwd slot j: t=L-2-j.
    float rg0[4], rg1[4], rg2[4], rg3[4];
#pragma unroll
    for (int j = 0; j < 4; j++) {
        if (unit == 0) {
            unsigned off = (unsigned)(1 + j) * EM_T;
            rg0[j] = __ldg(p00 + off); rg1[j] = __ldg(p01 + off);
            rg2[j] = __ldg(p10 + off); rg3[j] = __ldg(p11 + off);
        } else {
            int t0 = max(L0 - 2 - j, 0), t1 = max(L1 - 2 - j, 0);
            rg0[j] = __ldg(p00 + (unsigned)t0 * EM_T);
            rg1[j] = __ldg(p01 + (unsigned)t1 * EM_T);
            rg2[j] = __ldg(p10 + (unsigned)t0 * EM_T);
            rg3[j] = __ldg(p11 + (unsigned)t1 * EM_T);
        }
    }

    // smem store indices (uint16 units): elem (R,c) -> (R>>1)*16 + c*2 + (R&1)
    const int i00 = (R0 >> 1) * 16 + (R0 & 1) + 2 * c0;
    const int i01 = (R0 >> 1) * 16 + (R0 & 1) + 2 * c1;
    const int i10 = (R1 >> 1) * 16 + (R1 & 1) + 2 * c0;
    const int i11 = (R1 >> 1) * 16 + (R1 & 1) + 2 * c1;
    const int bidx = tig * 8 + gid;          // b-frag flat base in [32][8]

    // ---- initial store into vbuf[unit][0] ----
    {
        uint16_t* vbw = (uint16_t*)&vbuf[unit][0][0][0];
        if (unit == 0) {
            vbw[i00] = bf16b((1 <= S0) ? V0 : 0.0f);
            vbw[i01] = bf16b((1 <= S1) ? V1 : 0.0f);
            vbw[i10] = bf16b((1 <= S0) ? V2 : 0.0f);
            vbw[i11] = bf16b((1 <= S1) ? V3 : 0.0f);
        } else {
            // g1 = beta0 * e_{L-1}
            float e00 = __expf(__ldg(p00 + (unsigned)(L0 - 1) * EM_T));
            float e01 = __expf(__ldg(p01 + (unsigned)(L1 - 1) * EM_T));
            float e10 = __expf(__ldg(p10 + (unsigned)(L0 - 1) * EM_T));
            float e11 = __expf(__ldg(p11 + (unsigned)(L1 - 1) * EM_T));
            vbw[i00] = bf16b((1 <= S0) ? V0 * e00 : 0.0f);
            vbw[i01] = bf16b((1 <= S1) ? V1 * e01 : 0.0f);
            vbw[i10] = bf16b((1 <= S0) ? V2 * e10 : 0.0f);
            vbw[i11] = bf16b((1 <= S1) ? V3 * e11 : 0.0f);
        }
    }
    asm volatile("bar.sync %0, %1;" :: "r"(unit + 1), "r"(128) : "memory");

    // One tick: MMA from vbuf[rp], blend into f32 master, store vbuf[wp], bar.
#define TICK(i_, si_, rp_, wp_)                                                \
    do {                                                                       \
        const unsigned* Wr = &vbuf[unit][rp_][0][0];                           \
        float dA[4] = {0.f, 0.f, 0.f, 0.f};                                    \
        float dB[4] = {0.f, 0.f, 0.f, 0.f};                                    \
        mma16816(dA, afr[0], Wr[bidx],       Wr[bidx + 32]);                   \
        mma16816(dA, afr[1], Wr[bidx + 64],  Wr[bidx + 96]);                   \
        mma16816(dB, afr[2], Wr[bidx + 128], Wr[bidx + 160]);                  \
        mma16816(dB, afr[3], Wr[bidx + 192], Wr[bidx + 224]);                  \
        float e0 = __expf(rg0[si_]), e1 = __expf(rg1[si_]);                    \
        float e2 = __expf(rg2[si_]), e3 = __expf(rg3[si_]);                    \
        if (unit == 0) {                                                       \
            unsigned off = (unsigned)((i_) + 4) * EM_T;                        \
            rg0[si_] = __ldg(p00 + off); rg1[si_] = __ldg(p01 + off);          \
            rg2[si_] = __ldg(p10 + off); rg3[si_] = __ldg(p11 + off);          \
        } else {                                                               \
            int t0 = max(L0 - 5 - (i_), 0), t1 = max(L1 - 5 - (i_), 0);        \
            rg0[si_] = __ldg(p00 + (unsigned)t0 * EM_T);                       \
            rg1[si_] = __ldg(p01 + (unsigned)t1 * EM_T);                       \
            rg2[si_] = __ldg(p10 + (unsigned)t0 * EM_T);                       \
            rg3[si_] = __ldg(p11 + (unsigned)t1 * EM_T);                       \
        }                                                                      \
        bool A0 = (i_) <= S0, A1 = (i_) <= S1;                                 \
        float u0 = dA[0] + dB[0], u1 = dA[1] + dB[1];                          \
        float u2 = dA[2] + dB[2], u3 = dA[3] + dB[3];                          \
        if (unit == 0) {                                                       \
            V0 = A0 ? u0 * e0 : V0;  V1 = A1 ? u1 * e1 : V1;                   \
            V2 = A0 ? u2 * e2 : V2;  V3 = A1 ? u3 * e3 : V3;                   \
        } else {                                                               \
            V0 = A0 ? u0 : V0;  V1 = A1 ? u1 : V1;                             \
            V2 = A0 ? u2 : V2;  V3 = A1 ? u3 : V3;                             \
        }                                                                      \
        if ((((i_) & 7) == 0)) {                                               \
            float m0 = fmaxf(bf16lo_f(Wr[c0]), 1e-30f);                        \
            float m1 = fmaxf(bf16lo_f(Wr[c1]), 1e-30f);                        \
            float rv0 = A0 ? __fdividef(1.0f, m0) : 1.0f;                      \
            float rv1 = A1 ? __fdividef(1.0f, m1) : 1.0f;                      \
            Ca += A0 ? __logf(m0) : 0.0f;                                      \
            Cc += A1 ? __logf(m1) : 0.0f;                                      \
            V0 *= rv0; V2 *= rv0; V1 *= rv1; V3 *= rv1;                        \
        }                                                                      \
        bool N0 = (i_) + 1 <= S0, N1 = (i_) + 1 <= S1;                         \
        uint16_t* vbw = (uint16_t*)&vbuf[unit][wp_][0][0];                     \
        if (unit == 0) {                                                       \
            vbw[i00] = bf16b(N0 ? V0 : 0.0f);                                  \
            vbw[i01] = bf16b(N1 ? V1 : 0.0f);                                  \
            vbw[i10] = bf16b(N0 ? V2 : 0.0f);                                  \
            vbw[i11] = bf16b(N1 ? V3 : 0.0f);                                  \
        } else {                                                               \
            /* store g_{i+1} = beta_i * e_{L-1-i} (this tick's ring slot) */   \
            vbw[i00] = bf16b(N0 ? V0 * e0 : 0.0f);                             \
            vbw[i01] = bf16b(N1 ? V1 * e1 : 0.0f);                             \
            vbw[i10] = bf16b(N0 ? V2 * e2 : 0.0f);                             \
            vbw[i11] = bf16b(N1 ? V3 * e3 : 0.0f);                             \
        }                                                                      \
        asm volatile("bar.sync %0, %1;" :: "r"(unit + 1), "r"(128) : "memory");\
    } while (0)

    {
        const int nit = (Tmax + 3) >> 2;
        int i = 1;
        for (int it = 0; it < nit; it++, i += 4) {
            TICK(i,     0, 0, 1);
            TICK(i + 1, 1, 1, 0);
            TICK(i + 2, 2, 0, 1);
            TICK(i + 3, 3, 1, 0);
        }
    }

    // ---- meet & combine ----
    if (unit == 0) {
        meetA[R0][c0] = V0; meetA[R0][c1] = V1;
        meetA[R1][c0] = V2; meetA[R1][c1] = V3;
        if (wu == 0 && gid == 0) { sCf[c0] = Ca; sCf[c1] = Cc; }
    } else {
        meetB[R0][c0] = V0; meetB[R0][c1] = V1;
        meetB[R1][c0] = V2; meetB[R1][c1] = V3;
        if (wu == 0 && gid == 0) { sCb[c0] = Ca; sCb[c1] = Cc; }
    }
    __syncthreads();

    if (tid < 32) {
        int c = tid & 7, q = tid >> 3;
        float z = 0.0f;
#pragma unroll
        for (int s = 0; s < 16; s++)
            z += meetA[16 * q + s][c] * meetB[16 * q + s][c];
        z += __shfl_xor_sync(0xffffffffu, z, 8);
        z += __shfl_xor_sync(0xffffffffu, z, 16);
        if (tid < 8)
            out[bat[c]] = __logf(z) + sCf[c] + sCb[c]
                        + SHIFT_C * (float)(Lsh[c] - 1);
    }
}

extern "C" void kernel_launch(void* const* d_in, const int* in_sizes, int n_in,
                              void* d_out, int out_size)
{
    const float* em    = (const float*)d_in[0];
    const int*   seq   = (const int*)d_in[1];
    const float* start = (const float*)d_in[2];
    const float* stop  = (const float*)d_in[3];
    const float* trans = (const float*)d_in[4];
    float*       out   = (float*)d_out;

    rank_kernel<<<BATCH / 128, 128>>>(seq);
    crf_forward_kernel<<<BATCH / 8, 256>>>(em, seq, start, stop, trans, out);
}

// round 11
// speedup vs baseline: 1.0006x; 1.0006x over previous
#include <cuda_runtime.h>
#include <cuda_bf16.h>
#include <cstdint>

#define BATCH    1024
#define NS       64
#define EM_T     65536u      // floats per timestep (B*NS)
#define SHIFT_C  4.5f

__device__ int g_perm[BATCH];   // rank (desc by length) -> batch index

// ---- rank by length (descending), ties by index: perm is a bijection ----
__global__ void rank_kernel(const int* __restrict__ seq) {
    __shared__ int len[BATCH];
    const int tid = threadIdx.x;             // 128 threads
    for (int j = tid; j < BATCH; j += 128) len[j] = seq[j];
    __syncthreads();
    const int i  = blockIdx.x * 128 + tid;
    const int li = len[i];
    int r = 0;
#pragma unroll 8
    for (int j = 0; j < BATCH; j++) {
        int lj = len[j];
        r += (int)((lj > li) | ((lj == li) & (j < i)));
    }
    g_perm[r] = i;
}

__device__ __forceinline__ unsigned pack_bf2(float lo, float hi) {
    __nv_bfloat162 h = __floats2bfloat162_rn(lo, hi);
    return *reinterpret_cast<unsigned*>(&h);
}
__device__ __forceinline__ uint16_t bf16b(float x) {
    __nv_bfloat16 h = __float2bfloat16(x);
    return *reinterpret_cast<uint16_t*>(&h);
}
__device__ __forceinline__ float bf16lo_f(unsigned u) {
    __nv_bfloat162 h = *reinterpret_cast<__nv_bfloat162*>(&u);
    return __low2float(h);
}

__device__ __forceinline__ void mma16816(float* d, const unsigned* a,
                                         unsigned b0, unsigned b1) {
    asm("mma.sync.aligned.m16n8k16.row.col.f32.bf16.bf16.f32 "
        "{%0,%1,%2,%3}, {%4,%5,%6,%7}, {%8,%9}, {%0,%1,%2,%3};"
        : "+f"(d[0]), "+f"(d[1]), "+f"(d[2]), "+f"(d[3])
        : "r"(a[0]), "r"(a[1]), "r"(a[2]), "r"(a[3]), "r"(b0), "r"(b1));
}

// Block = one group of 8 length-sorted sequences. 256 thr: warps 0-3 = forward
// unit, warps 4-7 = backward unit. Each warp owns 16 output states. Per tick:
// V'[64x8] = E[64x64] @ V[64x8] via 4x mma.m16n8k16 (bf16 in, f32 accum),
// exchanged through a double-buffered smem tile. f32 master state per thread.
__global__ void __launch_bounds__(256, 1)
crf_forward_kernel(const float* __restrict__ em,
                   const int*   __restrict__ seq,
                   const float* __restrict__ start,
                   const float* __restrict__ stop,
                   const float* __restrict__ trans,
                   float*       __restrict__ out)
{
    __shared__ unsigned vbuf[2][2][32][8];   // [unit][parity][kpair][n]
    __shared__ float meetA[NS][8];
    __shared__ float meetB[NS][8];
    __shared__ float sCf[8], sCb[8];
    __shared__ int   bat[8], Lsh[8];

    const int tid  = threadIdx.x;
    const int w    = tid >> 5;
    const int lane = tid & 31;
    const int unit = w >> 2;                 // 0 fwd, 1 bwd
    const int wu   = w & 3;                  // warp-in-unit: rows [16wu,16wu+16)
    const int gid  = lane >> 2;              // 0..7
    const int tig  = lane & 3;               // 0..3

    if (tid < 8) {
        int b = g_perm[8 * blockIdx.x + tid];
        bat[tid] = b;
        Lsh[tid] = seq[b];
    }
    __syncthreads();

    const int c0 = 2 * tig, c1 = c0 + 1;     // my 2 columns (sequences)
    const int R0 = 16 * wu + gid, R1 = R0 + 8;  // my 2 output rows (states)
    const int b0 = bat[c0], b1 = bat[c1];
    const int L0 = Lsh[c0], L1 = Lsh[c1];
    // my role's step counts per column
    const int S0 = unit ? (L0 - 1 - (L0 >> 1)) : (L0 >> 1);
    const int S1 = unit ? (L1 - 1 - (L1 >> 1)) : (L1 >> 1);
    int Tmax = 0;
#pragma unroll
    for (int j = 0; j < 8; j++) {
        int Lj = Lsh[j];
        int s  = unit ? (Lj - 1 - (Lj >> 1)) : (Lj >> 1);
        Tmax = max(Tmax, s);
    }

    // ---- one-time A fragments: fwd rows of E, bwd rows of E^T ----
    unsigned afr[4][4];
    if (unit == 0) {
#pragma unroll
        for (int kt = 0; kt < 4; kt++) {
            int kc = 16 * kt + 2 * tig;
            float2 x0 = *(const float2*)(trans + R0 * NS + kc);
            float2 x1 = *(const float2*)(trans + R1 * NS + kc);
            float2 x2 = *(const float2*)(trans + R0 * NS + kc + 8);
            float2 x3 = *(const float2*)(trans + R1 * NS + kc + 8);
            afr[kt][0] = pack_bf2(__expf(x0.x - SHIFT_C), __expf(x0.y - SHIFT_C));
            afr[kt][1] = pack_bf2(__expf(x1.x - SHIFT_C), __expf(x1.y - SHIFT_C));
            afr[kt][2] = pack_bf2(__expf(x2.x - SHIFT_C), __expf(x2.y - SHIFT_C));
            afr[kt][3] = pack_bf2(__expf(x3.x - SHIFT_C), __expf(x3.y - SHIFT_C));
        }
    } else {
#pragma unroll
        for (int kt = 0; kt < 4; kt++) {
            int kc = 16 * kt + 2 * tig;
            afr[kt][0] = pack_bf2(__expf(__ldg(trans + kc * NS + R0) - SHIFT_C),
                                  __expf(__ldg(trans + (kc + 1) * NS + R0) - SHIFT_C));
            afr[kt][1] = pack_bf2(__expf(__ldg(trans + kc * NS + R1) - SHIFT_C),
                                  __expf(__ldg(trans + (kc + 1) * NS + R1) - SHIFT_C));
            afr[kt][2] = pack_bf2(__expf(__ldg(trans + (kc + 8) * NS + R0) - SHIFT_C),
                                  __expf(__ldg(trans + (kc + 9) * NS + R0) - SHIFT_C));
            afr[kt][3] = pack_bf2(__expf(__ldg(trans + (kc + 8) * NS + R1) - SHIFT_C),
                                  __expf(__ldg(trans + (kc + 9) * NS + R1) - SHIFT_C));
        }
    }

    // emission pointers for my 4 (row, col) elements: d0=(R0,c0) d1=(R0,c1) d2=(R1,c0) d3=(R1,c1)
    const float* p00 = em + (unsigned)b0 * NS + R0;
    const float* p01 = em + (unsigned)b1 * NS + R0;
    const float* p10 = em + (unsigned)b0 * NS + R1;
    const float* p11 = em + (unsigned)b1 * NS + R1;

    // f32 master state + per-column log-scale accumulators
    float V0, V1, V2, V3;
    float Ca = 0.0f, Cc = 0.0f;
    if (unit == 0) {
        float s0v = __ldg(start + R0), s1v = __ldg(start + R1);
        V0 = __expf(s0v + __ldg(p00));
        V1 = __expf(s0v + __ldg(p01));
        V2 = __expf(s1v + __ldg(p10));
        V3 = __expf(s1v + __ldg(p11));
    } else {
        float t0 = __expf(__ldg(stop + R0));
        float t1 = __expf(__ldg(stop + R1));
        V0 = t0; V1 = t1; V2 = t0; V3 = t1;
        // careful: d-order is (R0,c0),(R0,c1),(R1,c0),(R1,c1) -> stop depends on row only
        V0 = t0; V1 = t0; V2 = t1; V3 = t1;
    }

    // raw emission ring, 4 ticks deep. fwd slot j: t=1+j. bwd slot j: t=L-2-j.
    float rg0[4], rg1[4], rg2[4], rg3[4];
#pragma unroll
    for (int j = 0; j < 4; j++) {
        if (unit == 0) {
            unsigned off = (unsigned)(1 + j) * EM_T;
            rg0[j] = __ldg(p00 + off); rg1[j] = __ldg(p01 + off);
            rg2[j] = __ldg(p10 + off); rg3[j] = __ldg(p11 + off);
        } else {
            int t0 = max(L0 - 2 - j, 0), t1 = max(L1 - 2 - j, 0);
            rg0[j] = __ldg(p00 + (unsigned)t0 * EM_T);
            rg1[j] = __ldg(p01 + (unsigned)t1 * EM_T);
            rg2[j] = __ldg(p10 + (unsigned)t0 * EM_T);
            rg3[j] = __ldg(p11 + (unsigned)t1 * EM_T);
        }
    }

    // smem store indices (uint16 units): elem (R,c) -> (R>>1)*16 + c*2 + (R&1)
    const int i00 = (R0 >> 1) * 16 + (R0 & 1) + 2 * c0;
    const int i01 = (R0 >> 1) * 16 + (R0 & 1) + 2 * c1;
    const int i10 = (R1 >> 1) * 16 + (R1 & 1) + 2 * c0;
    const int i11 = (R1 >> 1) * 16 + (R1 & 1) + 2 * c1;
    const int bidx = tig * 8 + gid;          // b-frag flat base in [32][8]

    // ---- initial store into vbuf[unit][0] ----
    {
        uint16_t* vbw = (uint16_t*)&vbuf[unit][0][0][0];
        if (unit == 0) {
            vbw[i00] = bf16b((1 <= S0) ? V0 : 0.0f);
            vbw[i01] = bf16b((1 <= S1) ? V1 : 0.0f);
            vbw[i10] = bf16b((1 <= S0) ? V2 : 0.0f);
            vbw[i11] = bf16b((1 <= S1) ? V3 : 0.0f);
        } else {
            // g1 = beta0 * e_{L-1}
            float e00 = __expf(__ldg(p00 + (unsigned)(L0 - 1) * EM_T));
            float e01 = __expf(__ldg(p01 + (unsigned)(L1 - 1) * EM_T));
            float e10 = __expf(__ldg(p10 + (unsigned)(L0 - 1) * EM_T));
            float e11 = __expf(__ldg(p11 + (unsigned)(L1 - 1) * EM_T));
            vbw[i00] = bf16b((1 <= S0) ? V0 * e00 : 0.0f);
            vbw[i01] = bf16b((1 <= S1) ? V1 * e01 : 0.0f);
            vbw[i10] = bf16b((1 <= S0) ? V2 * e10 : 0.0f);
            vbw[i11] = bf16b((1 <= S1) ? V3 * e11 : 0.0f);
        }
    }
    asm volatile("bar.sync %0, %1;" :: "r"(unit + 1), "r"(128) : "memory");

    // One tick: MMA from vbuf[rp], blend into f32 master, store vbuf[wp], bar.
#define TICK(i_, si_, rp_, wp_)                                                \
    do {                                                                       \
        const unsigned* Wr = &vbuf[unit][rp_][0][0];                           \
        float dA[4] = {0.f, 0.f, 0.f, 0.f};                                    \
        float dB[4] = {0.f, 0.f, 0.f, 0.f};                                    \
        mma16816(dA, afr[0], Wr[bidx],       Wr[bidx + 32]);                   \
        mma16816(dA, afr[1], Wr[bidx + 64],  Wr[bidx + 96]);                   \
        mma16816(dB, afr[2], Wr[bidx + 128], Wr[bidx + 160]);                  \
        mma16816(dB, afr[3], Wr[bidx + 192], Wr[bidx + 224]);                  \
        float e0 = __expf(rg0[si_]), e1 = __expf(rg1[si_]);                    \
        float e2 = __expf(rg2[si_]), e3 = __expf(rg3[si_]);                    \
        if (unit == 0) {                                                       \
            unsigned off = (unsigned)((i_) + 4) * EM_T;                        \
            rg0[si_] = __ldg(p00 + off); rg1[si_] = __ldg(p01 + off);          \
            rg2[si_] = __ldg(p10 + off); rg3[si_] = __ldg(p11 + off);          \
        } else {                                                               \
            int t0 = max(L0 - 5 - (i_), 0), t1 = max(L1 - 5 - (i_), 0);        \
            rg0[si_] = __ldg(p00 + (unsigned)t0 * EM_T);                       \
            rg1[si_] = __ldg(p01 + (unsigned)t1 * EM_T);                       \
            rg2[si_] = __ldg(p10 + (unsigned)t0 * EM_T);                       \
            rg3[si_] = __ldg(p11 + (unsigned)t1 * EM_T);                       \
        }                                                                      \
        bool A0 = (i_) <= S0, A1 = (i_) <= S1;                                 \
        float u0 = dA[0] + dB[0], u1 = dA[1] + dB[1];                          \
        float u2 = dA[2] + dB[2], u3 = dA[3] + dB[3];                          \
        if (unit == 0) {                                                       \
            V0 = A0 ? u0 * e0 : V0;  V1 = A1 ? u1 * e1 : V1;                   \
            V2 = A0 ? u2 * e2 : V2;  V3 = A1 ? u3 * e3 : V3;                   \
        } else {                                                               \
            V0 = A0 ? u0 : V0;  V1 = A1 ? u1 : V1;                             \
            V2 = A0 ? u2 : V2;  V3 = A1 ? u3 : V3;                             \
        }                                                                      \
        if ((((i_) & 7) == 0)) {                                               \
            float m0 = fmaxf(bf16lo_f(Wr[c0]), 1e-30f);                        \
            float m1 = fmaxf(bf16lo_f(Wr[c1]), 1e-30f);                        \
            float rv0 = A0 ? __fdividef(1.0f, m0) : 1.0f;                      \
            float rv1 = A1 ? __fdividef(1.0f, m1) : 1.0f;                      \
            Ca += A0 ? __logf(m0) : 0.0f;                                      \
            Cc += A1 ? __logf(m1) : 0.0f;                                      \
            V0 *= rv0; V2 *= rv0; V1 *= rv1; V3 *= rv1;                        \
        }                                                                      \
        bool N0 = (i_) + 1 <= S0, N1 = (i_) + 1 <= S1;                         \
        uint16_t* vbw = (uint16_t*)&vbuf[unit][wp_][0][0];                     \
        if (unit == 0) {                                                       \
            vbw[i00] = bf16b(N0 ? V0 : 0.0f);                                  \
            vbw[i01] = bf16b(N1 ? V1 : 0.0f);                                  \
            vbw[i10] = bf16b(N0 ? V2 : 0.0f);                                  \
            vbw[i11] = bf16b(N1 ? V3 : 0.0f);                                  \
        } else {                                                               \
            /* store g_{i+1} = beta_i * e_{L-1-i} (this tick's ring slot) */   \
            vbw[i00] = bf16b(N0 ? V0 * e0 : 0.0f);                             \
            vbw[i01] = bf16b(N1 ? V1 * e1 : 0.0f);                             \
            vbw[i10] = bf16b(N0 ? V2 * e2 : 0.0f);                             \
            vbw[i11] = bf16b(N1 ? V3 * e3 : 0.0f);                             \
        }                                                                      \
        asm volatile("bar.sync %0, %1;" :: "r"(unit + 1), "r"(128) : "memory");\
    } while (0)

    {
        const int nit = (Tmax + 3) >> 2;
        int i = 1;
        for (int it = 0; it < nit; it++, i += 4) {
            TICK(i,     0, 0, 1);
            TICK(i + 1, 1, 1, 0);
            TICK(i + 2, 2, 0, 1);
            TICK(i + 3, 3, 1, 0);
        }
    }

    // ---- meet & combine ----
    if (unit == 0) {
        meetA[R0][c0] = V0; meetA[R0][c1] = V1;
        meetA[R1][c0] = V2; meetA[R1][c1] = V3;
        if (wu == 0 && gid == 0) { sCf[c0] = Ca; sCf[c1] = Cc; }
    } else {
        meetB[R0][c0] = V0; meetB[R0][c1] = V1;
        meetB[R1][c0] = V2; meetB[R1][c1] = V3;
        if (wu == 0 && gid == 0) { sCb[c0] = Ca; sCb[c1] = Cc; }
    }
    __syncthreads();

    if (tid < 32) {
        int c = tid & 7, q = tid >> 3;
        float z = 0.0f;
#pragma unroll
        for (int s = 0; s < 16; s++)
            z += meetA[16 * q + s][c] * meetB[16 * q + s][c];
        z += __shfl_xor_sync(0xffffffffu, z, 8);
        z += __shfl_xor_sync(0xffffffffu, z, 16);
        if (tid < 8)
            out[bat[c]] = __logf(z) + sCf[c] + sCb[c]
                        + SHIFT_C * (float)(Lsh[c] - 1);
    }
}

extern "C" void kernel_launch(void* const* d_in, const int* in_sizes, int n_in,
                              void* d_out, int out_size)
{
    const float* em    = (const float*)d_in[0];
    const int*   seq   = (const int*)d_in[1];
    const float* start = (const float*)d_in[2];
    const float* stop  = (const float*)d_in[3];
    const float* trans = (const float*)d_in[4];
    float*       out   = (float*)d_out;

    rank_kernel<<<BATCH / 128, 128>>>(seq);
    crf_forward_kernel<<<BATCH / 8, 256>>>(em, seq, start, stop, trans, out);
}